// round 2
// baseline (speedup 1.0000x reference)
#include <cuda_runtime.h>
#include <cstdint>

#define N_PTS   32768
#define DIM     256
#define KCODES  1024
#define DECAYF  0.99f
#define OMDECAY 0.01f
#define EPSF    1e-5f

// Output layout (concatenated, float32):
// z_q_st [N,D], vq_loss [1], indices [N], new_embedding [K,D],
// new_cluster_size [K], new_ema_w [K,D]
#define OFF_ZQ    0
#define OFF_LOSS  (N_PTS * DIM)                 // 8388608
#define OFF_IDX   (OFF_LOSS + 1)                // 8388609
#define OFF_EMB   (OFF_IDX + N_PTS)             // 8421377
#define OFF_CS    (OFF_EMB + KCODES * DIM)      // 8683521
#define OFF_EMAW  (OFF_CS + KCODES)             // 8684545

__device__ unsigned long long g_keys[N_PTS];
__device__ float g_enorm[KCODES];
__device__ float g_loss;
__device__ float g_n;

// ---------------------------------------------------------------------------
// Init: new_ema_w = decay*ema_w ; new_cs = decay*ema_cs ; keys = +inf ; loss=0
// ---------------------------------------------------------------------------
__global__ void k_init(const float* __restrict__ ema_cs,
                       const float* __restrict__ ema_w,
                       float* __restrict__ out) {
    int i = blockIdx.x * blockDim.x + threadIdx.x;   // grid covers 262144
    if (i < KCODES * DIM) out[OFF_EMAW + i] = DECAYF * ema_w[i];
    if (i < N_PTS)        g_keys[i] = 0xFFFFFFFFFFFFFFFFULL;
    if (i < KCODES)       out[OFF_CS + i] = DECAYF * ema_cs[i];
    if (i == 0)           g_loss = 0.0f;
}

// ---------------------------------------------------------------------------
// Per-code squared norms, one warp per code
// ---------------------------------------------------------------------------
__global__ void k_norm(const float* __restrict__ emb) {
    int warp = (blockIdx.x * blockDim.x + threadIdx.x) >> 5;
    int lane = threadIdx.x & 31;
    if (warp >= KCODES) return;
    const float4* row = (const float4*)(emb + (size_t)warp * DIM);
    float4 a = row[lane * 2 + 0];
    float4 b = row[lane * 2 + 1];
    float s = a.x*a.x + a.y*a.y + a.z*a.z + a.w*a.w
            + b.x*b.x + b.y*b.y + b.z*b.z + b.w*b.w;
#pragma unroll
    for (int off = 16; off; off >>= 1) s += __shfl_down_sync(0xFFFFFFFFu, s, off);
    if (lane == 0) g_enorm[warp] = s;
}

// ---------------------------------------------------------------------------
// Distance GEMM + fused argmin.
// Grid: (N/64, K/64). Block 256 thr, 4x4 register micro-tile, BK=16.
// dist = ||e||^2 - 2 * x.e  (||x||^2 irrelevant for argmin)
// Packed key atomicMin -> global per-point winner. Deterministic.
// ---------------------------------------------------------------------------
#define BM 64
#define BN 64
#define BK 16

__global__ __launch_bounds__(256) void k_dist(const float* __restrict__ z,
                                              const float* __restrict__ emb) {
    __shared__ float As[BK][BM];
    __shared__ float Bs[BK][BN];

    int tid = threadIdx.x;
    int tx = tid & 15;        // code dir
    int ty = tid >> 4;        // point dir
    int m0 = blockIdx.x * BM;
    int n0 = blockIdx.y * BN;

    float acc[4][4] = {};

    // global load mapping: thread -> (row 0..63, 4 consecutive d of 16)
    int lr = tid >> 2;
    int lc = (tid & 3) * 4;
    const float* zrow = z   + (size_t)(m0 + lr) * DIM;
    const float* erow = emb + (size_t)(n0 + lr) * DIM;

    for (int kk = 0; kk < DIM; kk += BK) {
        float4 av = *(const float4*)(zrow + kk + lc);
        float4 bv = *(const float4*)(erow + kk + lc);
        __syncthreads();
        As[lc + 0][lr] = av.x; As[lc + 1][lr] = av.y;
        As[lc + 2][lr] = av.z; As[lc + 3][lr] = av.w;
        Bs[lc + 0][lr] = bv.x; Bs[lc + 1][lr] = bv.y;
        Bs[lc + 2][lr] = bv.z; Bs[lc + 3][lr] = bv.w;
        __syncthreads();
#pragma unroll
        for (int k = 0; k < BK; k++) {
            float4 af = *(const float4*)(&As[k][ty * 4]);
            float4 bf = *(const float4*)(&Bs[k][tx * 4]);
            acc[0][0] += af.x * bf.x; acc[0][1] += af.x * bf.y;
            acc[0][2] += af.x * bf.z; acc[0][3] += af.x * bf.w;
            acc[1][0] += af.y * bf.x; acc[1][1] += af.y * bf.y;
            acc[1][2] += af.y * bf.z; acc[1][3] += af.y * bf.w;
            acc[2][0] += af.z * bf.x; acc[2][1] += af.z * bf.y;
            acc[2][2] += af.z * bf.z; acc[2][3] += af.z * bf.w;
            acc[3][0] += af.w * bf.x; acc[3][1] += af.w * bf.y;
            acc[3][2] += af.w * bf.z; acc[3][3] += af.w * bf.w;
        }
    }

    // epilogue: per-point min over this block's 64 codes, then global atomicMin
    float en[4];
#pragma unroll
    for (int j = 0; j < 4; j++) en[j] = g_enorm[n0 + tx * 4 + j];

#pragma unroll
    for (int i = 0; i < 4; i++) {
        unsigned long long best = 0xFFFFFFFFFFFFFFFFULL;
#pragma unroll
        for (int j = 0; j < 4; j++) {
            int c = n0 + tx * 4 + j;
            float d = en[j] - 2.0f * acc[i][j];
            unsigned int bits = __float_as_uint(d);
            unsigned int u = (bits & 0x80000000u) ? ~bits : (bits | 0x80000000u);
            unsigned long long key = ((unsigned long long)u << 32) | (unsigned int)c;
            if (key < best) best = key;
        }
        // reduce across the 16 threads sharing this point-row
#pragma unroll
        for (int off = 8; off; off >>= 1) {
            unsigned long long o = __shfl_down_sync(0xFFFFFFFFu, best, off, 16);
            if (o < best) best = o;
        }
        if (tx == 0) atomicMin(&g_keys[m0 + ty * 4 + i], best);
    }
}

// ---------------------------------------------------------------------------
// Gather z_q, write indices, accumulate loss + EMA scatter.
// One warp per point; 8 warps / block.
// ---------------------------------------------------------------------------
__global__ __launch_bounds__(256) void k_gather(const float* __restrict__ z,
                                                const float* __restrict__ emb,
                                                float* __restrict__ out) {
    __shared__ float warp_loss[8];
    int wip = threadIdx.x >> 5;          // warp in block
    int lane = threadIdx.x & 31;
    int n = blockIdx.x * 8 + wip;

    float lsum = 0.0f;
    if (n < N_PTS) {
        int k = (int)(g_keys[n] & 0xFFFFFFFFULL);
        const float4* zr = (const float4*)(z   + (size_t)n * DIM);
        const float4* er = (const float4*)(emb + (size_t)k * DIM);
        float4* zq = (float4*)(out + OFF_ZQ + (size_t)n * DIM);
        float* emaw = out + OFF_EMAW + (size_t)k * DIM;
#pragma unroll
        for (int j = 0; j < 2; j++) {
            int i4 = lane * 2 + j;
            float4 zv = zr[i4];
            float4 ev = er[i4];
            zq[i4] = ev;   // z_q_st == z_q numerically
            float dx = zv.x - ev.x, dy = zv.y - ev.y;
            float dz = zv.z - ev.z, dw = zv.w - ev.w;
            lsum += dx*dx + dy*dy + dz*dz + dw*dw;
            int d = i4 * 4;
            atomicAdd(emaw + d + 0, OMDECAY * zv.x);
            atomicAdd(emaw + d + 1, OMDECAY * zv.y);
            atomicAdd(emaw + d + 2, OMDECAY * zv.z);
            atomicAdd(emaw + d + 3, OMDECAY * zv.w);
        }
#pragma unroll
        for (int off = 16; off; off >>= 1)
            lsum += __shfl_down_sync(0xFFFFFFFFu, lsum, off);
        if (lane == 0) {
            atomicAdd(out + OFF_CS + k, OMDECAY);
            out[OFF_IDX + n] = (float)k;
        }
    }
    if (lane == 0) warp_loss[wip] = lsum;
    __syncthreads();
    if (threadIdx.x == 0) {
        float s = 0.0f;
#pragma unroll
        for (int w = 0; w < 8; w++) s += warp_loss[w];
        atomicAdd(&g_loss, s);
    }
}

// ---------------------------------------------------------------------------
// n = sum(new_cluster_size)  (single block of 1024)
// ---------------------------------------------------------------------------
__global__ void k_nsum(const float* __restrict__ out) {
    __shared__ float sh[32];
    int t = threadIdx.x;
    float v = out[OFF_CS + t];
#pragma unroll
    for (int off = 16; off; off >>= 1) v += __shfl_down_sync(0xFFFFFFFFu, v, off);
    if ((t & 31) == 0) sh[t >> 5] = v;
    __syncthreads();
    if (t < 32) {
        float s = sh[t];
#pragma unroll
        for (int off = 16; off; off >>= 1) s += __shfl_down_sync(0xFFFFFFFFu, s, off);
        if (t == 0) g_n = s;
    }
}

// ---------------------------------------------------------------------------
// Finalize: new_embedding = new_ema_w / laplace_smoothed_cs ; write loss
// ---------------------------------------------------------------------------
__global__ void k_final(float* __restrict__ out) {
    int i = blockIdx.x * blockDim.x + threadIdx.x;   // < 262144
    float n = g_n;
    int k = i >> 8;
    float cs = (out[OFF_CS + k] + EPSF) / (n + (float)KCODES * EPSF) * n;
    out[OFF_EMB + i] = out[OFF_EMAW + i] / cs;
    if (i == 0)
        out[OFF_LOSS] = 1.25f * g_loss / (float)(N_PTS * DIM);
}

// ---------------------------------------------------------------------------
extern "C" void kernel_launch(void* const* d_in, const int* in_sizes, int n_in,
                              void* d_out, int out_size) {
    const float* z      = (const float*)d_in[0];  // [32,32,32,256]
    const float* emb    = (const float*)d_in[1];  // [1024,256]
    const float* ema_cs = (const float*)d_in[2];  // [1024]
    const float* ema_w  = (const float*)d_in[3];  // [1024,256]
    float* out = (float*)d_out;

    k_init<<<(KCODES * DIM + 255) / 256, 256>>>(ema_cs, ema_w, out);
    k_norm<<<(KCODES * 32) / 256, 256>>>(emb);
    dim3 gdist(N_PTS / BM, KCODES / BN);
    k_dist<<<gdist, 256>>>(z, emb);
    k_gather<<<N_PTS / 8, 256>>>(z, emb, out);
    k_nsum<<<1, 1024>>>(out);
    k_final<<<(KCODES * DIM + 255) / 256, 256>>>(out);
}

// round 3
// speedup vs baseline: 1.0027x; 1.0027x over previous
#include <cuda_runtime.h>
#include <cstdint>

#define N_PTS   32768
#define DIM     256
#define KCODES  1024
#define DECAYF  0.99f
#define OMDECAY 0.01f
#define EPSF    1e-5f

// Output layout (concatenated, float32):
// z_q_st [N,D], vq_loss [1], indices [N], new_embedding [K,D],
// new_cluster_size [K], new_ema_w [K,D]
#define OFF_ZQ    0
#define OFF_LOSS  (N_PTS * DIM)                 // 8388608
#define OFF_IDX   (OFF_LOSS + 1)                // 8388609
#define OFF_EMB   (OFF_IDX + N_PTS)             // 8421377
#define OFF_CS    (OFF_EMB + KCODES * DIM)      // 8683521
#define OFF_EMAW  (OFF_CS + KCODES)             // 8684545

__device__ unsigned long long g_keys[N_PTS];
__device__ float g_enorm[KCODES];
__device__ float g_loss;
__device__ float g_n;

// ---------------------------------------------------------------------------
// Init: new_ema_w = decay*ema_w ; new_cs = decay*ema_cs ; keys = +inf ; loss=0
// ---------------------------------------------------------------------------
__global__ void k_init(const float* __restrict__ ema_cs,
                       const float* __restrict__ ema_w,
                       float* __restrict__ out) {
    int i = blockIdx.x * blockDim.x + threadIdx.x;   // grid covers 262144
    if (i < KCODES * DIM) out[OFF_EMAW + i] = DECAYF * ema_w[i];
    if (i < N_PTS)        g_keys[i] = 0xFFFFFFFFFFFFFFFFULL;
    if (i < KCODES)       out[OFF_CS + i] = DECAYF * ema_cs[i];
    if (i == 0)           g_loss = 0.0f;
}

// ---------------------------------------------------------------------------
// Per-code squared norms, one warp per code
// ---------------------------------------------------------------------------
__global__ void k_norm(const float* __restrict__ emb) {
    int warp = (blockIdx.x * blockDim.x + threadIdx.x) >> 5;
    int lane = threadIdx.x & 31;
    if (warp >= KCODES) return;
    const float4* row = (const float4*)(emb + (size_t)warp * DIM);
    float4 a = row[lane * 2 + 0];
    float4 b = row[lane * 2 + 1];
    float s = a.x*a.x + a.y*a.y + a.z*a.z + a.w*a.w
            + b.x*b.x + b.y*b.y + b.z*b.z + b.w*b.w;
#pragma unroll
    for (int off = 16; off; off >>= 1) s += __shfl_down_sync(0xFFFFFFFFu, s, off);
    if (lane == 0) g_enorm[warp] = s;
}

// ---------------------------------------------------------------------------
// Distance GEMM + fused argmin.
// Grid: (N/64, K/64). Block 256 thr, 4x4 register micro-tile, BK=16.
// dist = ||e||^2 - 2 * x.e  (||x||^2 irrelevant for argmin)
// Packed key atomicMin -> global per-point winner. Deterministic.
// ---------------------------------------------------------------------------
#define BM 64
#define BN 64
#define BK 16

__global__ __launch_bounds__(256) void k_dist(const float* __restrict__ z,
                                              const float* __restrict__ emb) {
    __shared__ float As[BK][BM];
    __shared__ float Bs[BK][BN];

    int tid = threadIdx.x;
    int tx = tid & 15;        // code dir
    int ty = tid >> 4;        // point dir
    int m0 = blockIdx.x * BM;
    int n0 = blockIdx.y * BN;

    float acc[4][4] = {};

    // global load mapping: thread -> (row 0..63, 4 consecutive d of 16)
    int lr = tid >> 2;
    int lc = (tid & 3) * 4;
    const float* zrow = z   + (size_t)(m0 + lr) * DIM;
    const float* erow = emb + (size_t)(n0 + lr) * DIM;

    for (int kk = 0; kk < DIM; kk += BK) {
        float4 av = *(const float4*)(zrow + kk + lc);
        float4 bv = *(const float4*)(erow + kk + lc);
        __syncthreads();
        As[lc + 0][lr] = av.x; As[lc + 1][lr] = av.y;
        As[lc + 2][lr] = av.z; As[lc + 3][lr] = av.w;
        Bs[lc + 0][lr] = bv.x; Bs[lc + 1][lr] = bv.y;
        Bs[lc + 2][lr] = bv.z; Bs[lc + 3][lr] = bv.w;
        __syncthreads();
#pragma unroll
        for (int k = 0; k < BK; k++) {
            float4 af = *(const float4*)(&As[k][ty * 4]);
            float4 bf = *(const float4*)(&Bs[k][tx * 4]);
            acc[0][0] += af.x * bf.x; acc[0][1] += af.x * bf.y;
            acc[0][2] += af.x * bf.z; acc[0][3] += af.x * bf.w;
            acc[1][0] += af.y * bf.x; acc[1][1] += af.y * bf.y;
            acc[1][2] += af.y * bf.z; acc[1][3] += af.y * bf.w;
            acc[2][0] += af.z * bf.x; acc[2][1] += af.z * bf.y;
            acc[2][2] += af.z * bf.z; acc[2][3] += af.z * bf.w;
            acc[3][0] += af.w * bf.x; acc[3][1] += af.w * bf.y;
            acc[3][2] += af.w * bf.z; acc[3][3] += af.w * bf.w;
        }
    }

    // epilogue: per-point min over this block's 64 codes, then global atomicMin
    float en[4];
#pragma unroll
    for (int j = 0; j < 4; j++) en[j] = g_enorm[n0 + tx * 4 + j];

#pragma unroll
    for (int i = 0; i < 4; i++) {
        unsigned long long best = 0xFFFFFFFFFFFFFFFFULL;
#pragma unroll
        for (int j = 0; j < 4; j++) {
            int c = n0 + tx * 4 + j;
            float d = en[j] - 2.0f * acc[i][j];
            unsigned int bits = __float_as_uint(d);
            unsigned int u = (bits & 0x80000000u) ? ~bits : (bits | 0x80000000u);
            unsigned long long key = ((unsigned long long)u << 32) | (unsigned int)c;
            if (key < best) best = key;
        }
        // reduce across the 16 threads sharing this point-row
#pragma unroll
        for (int off = 8; off; off >>= 1) {
            unsigned long long o = __shfl_down_sync(0xFFFFFFFFu, best, off, 16);
            if (o < best) best = o;
        }
        if (tx == 0) atomicMin(&g_keys[m0 + ty * 4 + i], best);
    }
}

// ---------------------------------------------------------------------------
// Gather z_q, write indices, accumulate loss + EMA scatter.
// One warp per point; 8 warps / block.
// ---------------------------------------------------------------------------
__global__ __launch_bounds__(256) void k_gather(const float* __restrict__ z,
                                                const float* __restrict__ emb,
                                                float* __restrict__ out) {
    __shared__ float warp_loss[8];
    int wip = threadIdx.x >> 5;          // warp in block
    int lane = threadIdx.x & 31;
    int n = blockIdx.x * 8 + wip;

    float lsum = 0.0f;
    if (n < N_PTS) {
        int k = (int)(g_keys[n] & 0xFFFFFFFFULL);
        const float4* zr = (const float4*)(z   + (size_t)n * DIM);
        const float4* er = (const float4*)(emb + (size_t)k * DIM);
        float4* zq = (float4*)(out + OFF_ZQ + (size_t)n * DIM);
        float* emaw = out + OFF_EMAW + (size_t)k * DIM;
#pragma unroll
        for (int j = 0; j < 2; j++) {
            int i4 = lane * 2 + j;
            float4 zv = zr[i4];
            float4 ev = er[i4];
            zq[i4] = ev;   // z_q_st == z_q numerically
            float dx = zv.x - ev.x, dy = zv.y - ev.y;
            float dz = zv.z - ev.z, dw = zv.w - ev.w;
            lsum += dx*dx + dy*dy + dz*dz + dw*dw;
            int d = i4 * 4;
            atomicAdd(emaw + d + 0, OMDECAY * zv.x);
            atomicAdd(emaw + d + 1, OMDECAY * zv.y);
            atomicAdd(emaw + d + 2, OMDECAY * zv.z);
            atomicAdd(emaw + d + 3, OMDECAY * zv.w);
        }
#pragma unroll
        for (int off = 16; off; off >>= 1)
            lsum += __shfl_down_sync(0xFFFFFFFFu, lsum, off);
        if (lane == 0) {
            atomicAdd(out + OFF_CS + k, OMDECAY);
            out[OFF_IDX + n] = (float)k;
        }
    }
    if (lane == 0) warp_loss[wip] = lsum;
    __syncthreads();
    if (threadIdx.x == 0) {
        float s = 0.0f;
#pragma unroll
        for (int w = 0; w < 8; w++) s += warp_loss[w];
        atomicAdd(&g_loss, s);
    }
}

// ---------------------------------------------------------------------------
// n = sum(new_cluster_size)  (single block of 1024)
// ---------------------------------------------------------------------------
__global__ void k_nsum(const float* __restrict__ out) {
    __shared__ float sh[32];
    int t = threadIdx.x;
    float v = out[OFF_CS + t];
#pragma unroll
    for (int off = 16; off; off >>= 1) v += __shfl_down_sync(0xFFFFFFFFu, v, off);
    if ((t & 31) == 0) sh[t >> 5] = v;
    __syncthreads();
    if (t < 32) {
        float s = sh[t];
#pragma unroll
        for (int off = 16; off; off >>= 1) s += __shfl_down_sync(0xFFFFFFFFu, s, off);
        if (t == 0) g_n = s;
    }
}

// ---------------------------------------------------------------------------
// Finalize: new_embedding = new_ema_w / laplace_smoothed_cs ; write loss
// ---------------------------------------------------------------------------
__global__ void k_final(float* __restrict__ out) {
    int i = blockIdx.x * blockDim.x + threadIdx.x;   // < 262144
    float n = g_n;
    int k = i >> 8;
    float cs = (out[OFF_CS + k] + EPSF) / (n + (float)KCODES * EPSF) * n;
    out[OFF_EMB + i] = out[OFF_EMAW + i] / cs;
    if (i == 0)
        out[OFF_LOSS] = 1.25f * g_loss / (float)(N_PTS * DIM);
}

// ---------------------------------------------------------------------------
extern "C" void kernel_launch(void* const* d_in, const int* in_sizes, int n_in,
                              void* d_out, int out_size) {
    const float* z      = (const float*)d_in[0];  // [32,32,32,256]
    const float* emb    = (const float*)d_in[1];  // [1024,256]
    const float* ema_cs = (const float*)d_in[2];  // [1024]
    const float* ema_w  = (const float*)d_in[3];  // [1024,256]
    float* out = (float*)d_out;

    k_init<<<(KCODES * DIM + 255) / 256, 256>>>(ema_cs, ema_w, out);
    k_norm<<<(KCODES * 32) / 256, 256>>>(emb);
    dim3 gdist(N_PTS / BM, KCODES / BN);
    k_dist<<<gdist, 256>>>(z, emb);
    k_gather<<<N_PTS / 8, 256>>>(z, emb, out);
    k_nsum<<<1, 1024>>>(out);
    k_final<<<(KCODES * DIM + 255) / 256, 256>>>(out);
}